// round 1
// baseline (speedup 1.0000x reference)
#include <cuda_runtime.h>
#include <math.h>

#define HID   1024
#define NHEAD 16
#define HDIM  64
#define BB    8
#define LQ    16
#define LK    8192
#define RPB   (NHEAD*LQ)   /* 256 rows per batch: r = h*16 + q */

// ---------------- scratch (device globals; no allocation allowed) ----------------
__device__ float g_q[BB*LQ*HID];                    // projected queries [128][1024]
__device__ float g_qk[BB*RPB*HID];                  // scale * q_h @ Wk_h  [8][256][1024]
__device__ float g_logits[(size_t)BB*RPB*LK];       // logits / probs in place [8][256][8192]
__device__ float g_ctx[2*BB*RPB*HID];               // split-K=2 partial ctx [16][256][1024]
__device__ float g_attn[BB*LQ*HID];                 // per-head V-projected ctx [128][1024]

// =====================================================================
// Generic NT GEMM: C[m][n] = sum_k A[m*lda+k] * B[n*ldb+k]  (+ bias[n])
// Grid covers M,N exactly: grid.x = N/BN, grid.y = M/BM, grid.z = batch
// =====================================================================
template<int BM,int BN,int BK,int TM,int TN,bool BIAS>
__global__ void __launch_bounds__((BM/TM)*(BN/TN))
gemm_nt(const float* __restrict__ A, const float* __restrict__ Bm,
        const float* __restrict__ bias, float* __restrict__ C,
        int K, int lda, int ldb, int ldc,
        long sA, long sB, long sC)
{
    constexpr int TX = BN/TN, TY = BM/TM, NT = TX*TY;
    const int tid = threadIdx.x;
    const int tx  = tid % TX, ty = tid / TX;
    const int bm  = blockIdx.y*BM, bn = blockIdx.x*BN;
    A  += (long)blockIdx.z * sA;
    Bm += (long)blockIdx.z * sB;
    C  += (long)blockIdx.z * sC;

    __shared__ float As[BK][BM+4];
    __shared__ float Bs[BK][BN+4];

    float acc[TM][TN];
#pragma unroll
    for (int i=0;i<TM;i++)
#pragma unroll
        for (int j=0;j<TN;j++) acc[i][j] = 0.f;

    for (int k0 = 0; k0 < K; k0 += BK) {
        // A tile: BM x BK (k contiguous) -> As[k][m]
#pragma unroll
        for (int i = tid; i < BM*BK/4; i += NT) {
            int m  = i / (BK/4);
            int k4 = (i % (BK/4)) * 4;
            float4 v = *reinterpret_cast<const float4*>(&A[(long)(bm+m)*lda + k0 + k4]);
            As[k4+0][m] = v.x; As[k4+1][m] = v.y; As[k4+2][m] = v.z; As[k4+3][m] = v.w;
        }
        // B tile: BN x BK (k contiguous) -> Bs[k][n]
#pragma unroll
        for (int i = tid; i < BN*BK/4; i += NT) {
            int n  = i / (BK/4);
            int k4 = (i % (BK/4)) * 4;
            float4 v = *reinterpret_cast<const float4*>(&Bm[(long)(bn+n)*ldb + k0 + k4]);
            Bs[k4+0][n] = v.x; Bs[k4+1][n] = v.y; Bs[k4+2][n] = v.z; Bs[k4+3][n] = v.w;
        }
        __syncthreads();
#pragma unroll
        for (int k = 0; k < BK; k++) {
            float af[TM], bf[TN];
#pragma unroll
            for (int i=0;i<TM;i+=4)
                *reinterpret_cast<float4*>(&af[i]) =
                    *reinterpret_cast<const float4*>(&As[k][ty*TM + i]);
#pragma unroll
            for (int j=0;j<TN;j+=4)
                *reinterpret_cast<float4*>(&bf[j]) =
                    *reinterpret_cast<const float4*>(&Bs[k][tx*TN + j]);
#pragma unroll
            for (int i=0;i<TM;i++)
#pragma unroll
                for (int j=0;j<TN;j++)
                    acc[i][j] = fmaf(af[i], bf[j], acc[i][j]);
        }
        __syncthreads();
    }

#pragma unroll
    for (int i=0;i<TM;i++) {
        const int m = bm + ty*TM + i;
        float* crow = &C[(long)m*ldc + bn + tx*TN];
#pragma unroll
        for (int j=0;j<TN;j+=4) {
            float4 v;
            v.x = acc[i][j+0]; v.y = acc[i][j+1]; v.z = acc[i][j+2]; v.w = acc[i][j+3];
            if (BIAS) {
                const float* bp = &bias[bn + tx*TN + j];
                v.x += bp[0]; v.y += bp[1]; v.z += bp[2]; v.w += bp[3];
            }
            *reinterpret_cast<float4*>(&crow[j]) = v;
        }
    }
}

// =====================================================================
// Generic NN GEMM with split-K: C[m][n] = sum_k A[m*lda+k] * B[k*ldb+n]
// grid.z = batch*ksplit; z -> (batch = z/ksplit, part = z%ksplit)
// Each part reduces Kpart and writes its own C slab (stride sC per z).
// =====================================================================
template<int BM,int BN,int BK,int TM,int TN>
__global__ void __launch_bounds__((BM/TM)*(BN/TN))
gemm_nn(const float* __restrict__ A, const float* __restrict__ Bm,
        float* __restrict__ C,
        int Kpart, int lda, int ldb, int ldc,
        long sA, long sB, long sC, int ksplit)
{
    constexpr int TX = BN/TN, TY = BM/TM, NT = TX*TY;
    const int tid = threadIdx.x;
    const int tx  = tid % TX, ty = tid / TX;
    const int bm  = blockIdx.y*BM, bn = blockIdx.x*BN;
    const int batch = blockIdx.z / ksplit;
    const int part  = blockIdx.z % ksplit;
    A  += (long)batch * sA + (long)part * Kpart;          // k offset in A
    Bm += (long)batch * sB + (long)part * Kpart * ldb;    // k offset in B rows
    C  += (long)blockIdx.z * sC;

    __shared__ float As[BK][BM+4];
    __shared__ float Bs[BK][BN+4];

    float acc[TM][TN];
#pragma unroll
    for (int i=0;i<TM;i++)
#pragma unroll
        for (int j=0;j<TN;j++) acc[i][j] = 0.f;

    for (int k0 = 0; k0 < Kpart; k0 += BK) {
#pragma unroll
        for (int i = tid; i < BM*BK/4; i += NT) {
            int m  = i / (BK/4);
            int k4 = (i % (BK/4)) * 4;
            float4 v = *reinterpret_cast<const float4*>(&A[(long)(bm+m)*lda + k0 + k4]);
            As[k4+0][m] = v.x; As[k4+1][m] = v.y; As[k4+2][m] = v.z; As[k4+3][m] = v.w;
        }
#pragma unroll
        for (int i = tid; i < BK*BN/4; i += NT) {
            int k  = i / (BN/4);
            int n4 = (i % (BN/4)) * 4;
            float4 v = *reinterpret_cast<const float4*>(&Bm[(long)(k0+k)*ldb + bn + n4]);
            *reinterpret_cast<float4*>(&Bs[k][n4]) = v;
        }
        __syncthreads();
#pragma unroll
        for (int k = 0; k < BK; k++) {
            float af[TM], bf[TN];
#pragma unroll
            for (int i=0;i<TM;i+=4)
                *reinterpret_cast<float4*>(&af[i]) =
                    *reinterpret_cast<const float4*>(&As[k][ty*TM + i]);
#pragma unroll
            for (int j=0;j<TN;j+=4)
                *reinterpret_cast<float4*>(&bf[j]) =
                    *reinterpret_cast<const float4*>(&Bs[k][tx*TN + j]);
#pragma unroll
            for (int i=0;i<TM;i++)
#pragma unroll
                for (int j=0;j<TN;j++)
                    acc[i][j] = fmaf(af[i], bf[j], acc[i][j]);
        }
        __syncthreads();
    }

#pragma unroll
    for (int i=0;i<TM;i++) {
        const int m = bm + ty*TM + i;
        float* crow = &C[(long)m*ldc + bn + tx*TN];
#pragma unroll
        for (int j=0;j<TN;j+=4) {
            float4 v;
            v.x = acc[i][j+0]; v.y = acc[i][j+1]; v.z = acc[i][j+2]; v.w = acc[i][j+3];
            *reinterpret_cast<float4*>(&crow[j]) = v;
        }
    }
}

// =====================================================================
// qk = scale * q_h @ Wk_h : per (b,h) a 16 x 1024 output, K = 64
// qk[b][h*16+q][d] = 0.125 * sum_e g_q[b*16+q][h*64+e] * Wk[h*64+e][d]
// grid (HID/128, B*NHEAD), 128 threads
// =====================================================================
__global__ void qk_kernel(const float* __restrict__ q,
                          const float* __restrict__ Wk,
                          float* __restrict__ qk)
{
    const int bh = blockIdx.y;
    const int b = bh >> 4, h = bh & 15;
    const int col = blockIdx.x*128 + threadIdx.x;
    __shared__ float a[LQ][HDIM];
    for (int i = threadIdx.x; i < LQ*HDIM; i += 128) {
        int qq = i >> 6, e = i & 63;
        a[qq][e] = q[(b*LQ + qq)*HID + h*HDIM + e];
    }
    __syncthreads();
    float acc[LQ];
#pragma unroll
    for (int i=0;i<LQ;i++) acc[i] = 0.f;
#pragma unroll 8
    for (int e = 0; e < HDIM; e++) {
        float w = Wk[(h*HDIM + e)*HID + col];
#pragma unroll
        for (int qq = 0; qq < LQ; qq++) acc[qq] = fmaf(a[qq][e], w, acc[qq]);
    }
    const float scale = 0.125f;   // 1/sqrt(HDIM)
#pragma unroll
    for (int qq = 0; qq < LQ; qq++)
        qk[((long)b*RPB + h*LQ + qq)*HID + col] = acc[qq] * scale;
}

// =====================================================================
// In-place row softmax over LK=8192. One block (256 thr) per row; row
// staged once in 32 KB SMEM so gmem traffic is exactly 1 read + 1 write.
// =====================================================================
__global__ void softmax_kernel(float* __restrict__ logits)
{
    const size_t row = blockIdx.x;
    float* p = logits + row * (size_t)LK;
    __shared__ float buf[LK];
    __shared__ float red[8];
    const int tid = threadIdx.x;
    const int lane = tid & 31, warp = tid >> 5;
    float4*       b4 = reinterpret_cast<float4*>(buf);
    const float4* p4 = reinterpret_cast<const float4*>(p);

    float mx = -3.0e38f;
    for (int i = tid; i < LK/4; i += 256) {
        float4 v = p4[i]; b4[i] = v;
        mx = fmaxf(mx, fmaxf(fmaxf(v.x,v.y), fmaxf(v.z,v.w)));
    }
#pragma unroll
    for (int o=16;o;o>>=1) mx = fmaxf(mx, __shfl_xor_sync(0xffffffffu, mx, o));
    if (lane==0) red[warp] = mx;
    __syncthreads();
    mx = red[0];
#pragma unroll
    for (int w=1;w<8;w++) mx = fmaxf(mx, red[w]);

    float sum = 0.f;
    for (int i = tid; i < LK/4; i += 256) {
        float4 v = b4[i];
        v.x = expf(v.x - mx); v.y = expf(v.y - mx);
        v.z = expf(v.z - mx); v.w = expf(v.w - mx);
        b4[i] = v;
        sum += (v.x + v.y) + (v.z + v.w);
    }
#pragma unroll
    for (int o=16;o;o>>=1) sum += __shfl_xor_sync(0xffffffffu, sum, o);
    __syncthreads();                  // red[] still being read above
    if (lane==0) red[warp] = sum;
    __syncthreads();
    sum = 0.f;
#pragma unroll
    for (int w=0;w<8;w++) sum += red[w];
    const float inv = 1.f / sum;

    float4* o4 = reinterpret_cast<float4*>(p);
    for (int i = tid; i < LK/4; i += 256) {
        float4 v = b4[i];
        v.x *= inv; v.y *= inv; v.z *= inv; v.w *= inv;
        o4[i] = v;
    }
}

// =====================================================================
// attn[b*16+q][h*64+d] = sum_e (ctxA+ctxB)[b][h*16+q][e] * Wv[h*64+d][e] + bv
// grid = B*NHEAD blocks, 256 threads (d = t&63, qgroup = t>>6 covers 4 q's)
// =====================================================================
__global__ void attnv_kernel(const float* __restrict__ ctx,
                             const float* __restrict__ Wv,
                             const float* __restrict__ bv,
                             float* __restrict__ attn)
{
    const int bh = blockIdx.x;
    const int b = bh >> 4, h = bh & 15;
    const int t = threadIdx.x;
    const int d = t & 63, qg = t >> 6;      // qg in 0..3
    __shared__ float cs[LQ][129];
    __shared__ float ws[HDIM][129];
    float acc[4] = {0.f,0.f,0.f,0.f};

    const long rowA = (long)(b*2    )*RPB + h*LQ;
    const long rowB = (long)(b*2 + 1)*RPB + h*LQ;

    for (int e0 = 0; e0 < HID; e0 += 128) {
        __syncthreads();
        for (int i = t; i < LQ*128; i += 256) {
            int qq = i >> 7, e = i & 127;
            cs[qq][e] = ctx[(rowA + qq)*HID + e0 + e] + ctx[(rowB + qq)*HID + e0 + e];
        }
        for (int i = t; i < HDIM*128; i += 256) {
            int dd = i >> 7, e = i & 127;
            ws[dd][e] = Wv[(long)(h*HDIM + dd)*HID + e0 + e];
        }
        __syncthreads();
#pragma unroll 4
        for (int e = 0; e < 128; e++) {
            float w = ws[d][e];
#pragma unroll
            for (int j = 0; j < 4; j++)
                acc[j] = fmaf(cs[qg*4 + j][e], w, acc[j]);
        }
    }
    const float bvv = bv[h*HDIM + d];
#pragma unroll
    for (int j = 0; j < 4; j++)
        attn[(long)(b*LQ + qg*4 + j)*HID + h*HDIM + d] = acc[j] + bvv;
}

// =====================================================================
// launch
// =====================================================================
extern "C" void kernel_launch(void* const* d_in, const int* in_sizes, int n_in,
                              void* d_out, int out_size)
{
    const float* query = (const float*)d_in[0];
    const float* key   = (const float*)d_in[1];
    const float* value = (const float*)d_in[2];
    const float* Wq    = (const float*)d_in[3];
    const float* bq    = (const float*)d_in[4];
    const float* Wk    = (const float*)d_in[5];
    /* bk = d_in[6] : constant per softmax row -> softmax-invariant, dropped */
    const float* Wv    = (const float*)d_in[7];
    const float* bv    = (const float*)d_in[8];
    const float* Wo    = (const float*)d_in[9];
    const float* bo    = (const float*)d_in[10];
    float* out = (float*)d_out;

    float *gq, *gqk, *glog, *gctx, *gattn;
    cudaGetSymbolAddress((void**)&gq,    g_q);
    cudaGetSymbolAddress((void**)&gqk,   g_qk);
    cudaGetSymbolAddress((void**)&glog,  g_logits);
    cudaGetSymbolAddress((void**)&gctx,  g_ctx);
    cudaGetSymbolAddress((void**)&gattn, g_attn);

    // K1: q = query @ Wq^T + bq     [128 x 1024], K=1024
    gemm_nt<64,64,16,4,4,true><<<dim3(HID/64, (BB*LQ)/64, 1), 256>>>(
        query, Wq, bq, gq, HID, HID, HID, HID, 0, 0, 0);

    // K2: qk = scale * q_h @ Wk_h   [8][256][1024]
    qk_kernel<<<dim3(HID/128, BB*NHEAD), 128>>>(gq, Wk, gqk);

    // K3: logits = qk @ key^T       per batch [256 x 8192], K=1024
    gemm_nt<128,128,16,8,8,false><<<dim3(LK/128, RPB/128, BB), 256>>>(
        gqk, key, nullptr, glog, HID, HID, HID, LK,
        (long)RPB*HID, (long)LK*HID, (long)RPB*LK);

    // K4: row softmax in place      2048 rows of 8192
    softmax_kernel<<<BB*RPB, 256>>>(glog);

    // K5: ctx = probs @ value       per batch [256 x 1024], K=8192, split-K=2
    gemm_nn<128,128,16,8,8><<<dim3(HID/128, RPB/128, BB*2), 256>>>(
        glog, value, gctx, LK/2, LK, HID, HID,
        (long)RPB*LK, (long)LK*HID, (long)RPB*HID, 2);

    // K6: attn = ctx @ Wv_h^T + bv  [128 x 1024]
    attnv_kernel<<<BB*NHEAD, 256>>>(gctx, Wv, bv, gattn);

    // K7: out = attn @ Wo^T + bo    [128 x 1024], K=1024
    gemm_nt<64,64,16,4,4,true><<<dim3(HID/64, (BB*LQ)/64, 1), 256>>>(
        gattn, Wo, bo, out, HID, HID, HID, HID, 0, 0, 0);
}

// round 2
// speedup vs baseline: 1.9883x; 1.9883x over previous
#include <cuda_runtime.h>
#include <math.h>

#define HID   1024
#define NHEAD 16
#define HDIM  64
#define BB    8
#define LQ    16
#define LK    8192
#define RPB   (NHEAD*LQ)   /* 256 rows per batch: r = h*16 + q */

// ---------------- scratch (device globals; no allocation allowed) ----------------
__device__ float g_q[BB*LQ*HID];                    // projected queries [128][1024]
__device__ float g_qk[BB*RPB*HID];                  // scale * q_h @ Wk_h  [8][256][1024]
__device__ float g_logits[(size_t)BB*RPB*LK];       // logits / probs in place [8][256][8192]
__device__ float g_ctx[2*BB*RPB*HID];               // split-K=2 partial ctx [16][256][1024]
__device__ float g_attn[BB*LQ*HID];                 // per-head V-projected ctx [128][1024]

// =====================================================================
// helpers: tf32 convert + m16n8k8 tf32 mma
// =====================================================================
__device__ __forceinline__ unsigned f2tf(float x) {
    unsigned u;
    asm("cvt.rna.tf32.f32 %0, %1;" : "=r"(u) : "f"(x));
    return u;
}

__device__ __forceinline__ void mma_tf32(float c[4], const unsigned a[4], const unsigned b[2]) {
    asm("mma.sync.aligned.m16n8k8.row.col.f32.tf32.tf32.f32 "
        "{%0,%1,%2,%3}, {%4,%5,%6,%7}, {%8,%9}, {%0,%1,%2,%3};"
        : "+f"(c[0]), "+f"(c[1]), "+f"(c[2]), "+f"(c[3])
        : "r"(a[0]), "r"(a[1]), "r"(a[2]), "r"(a[3]), "r"(b[0]), "r"(b[1]));
}

// =====================================================================
// tf32 tensor-core GEMM, BM=256 (full M), BN=64, BK=16, 256 threads.
// LAYB=0: B global is [n][k] k-contiguous (NT, for logits = qk @ key^T)
// LAYB=1: B global is [k][n] n-contiguous (NN, for ctx = probs @ value)
// C[m][n] = sum_k A[m][k]*B[..], per blockIdx.z slab (batch and/or split-K).
// =====================================================================
template<int LAYB>
__global__ void __launch_bounds__(256, 2)
gemm_tf32(const float* __restrict__ A, const float* __restrict__ B,
          float* __restrict__ C, int Kpart, int lda, int ldb, int ldc,
          long sA, long sB, long sC, int ksplit)
{
    constexpr int BM = 256, BN = 64, BK = 16;
    constexpr int SA = BK + 4;          // As row stride (conflict-free frag reads)
    constexpr int SBNT = BK + 4;        // Bs[n][k] stride
    constexpr int SBNN = BN + 4;        // Bs[k][n] stride
    constexpr int BSSZ = (LAYB == 0) ? BN * SBNT : BK * SBNN;

    const int tid = threadIdx.x;
    const int bn  = blockIdx.x * BN;
    const int batch = blockIdx.z / ksplit;
    const int part  = blockIdx.z % ksplit;
    A += (long)batch * sA + (long)part * Kpart;
    if (LAYB == 0) B += (long)batch * sB + (long)part * Kpart;
    else           B += (long)batch * sB + (long)part * Kpart * ldb;
    C += (long)blockIdx.z * sC;

    __shared__ __align__(16) unsigned As[BM * SA];
    __shared__ __align__(16) unsigned Bs[BSSZ];

    // staging coordinates
    const int a_m0 = tid >> 2;                 // + j*64
    const int a_k  = (tid & 3) * 4;
    const int bnt_n = tid >> 2;                // NT: n row in tile
    const int bnt_k = (tid & 3) * 4;
    const int bnn_k = tid >> 4;                // NN: k row in tile
    const int bnn_n = (tid & 15) * 4;

    // warp/lane coordinates
    const int w    = tid >> 5;
    const int lane = tid & 31;
    const int wm   = (w >> 1) * 64;            // warp m origin (4 warps in m)
    const int wn   = (w & 1) * 32;             // warp n origin (2 warps in n)
    const int g    = lane >> 2;                // 0..7
    const int tg   = lane & 3;                 // 0..3

    float acc[4][4][4];
#pragma unroll
    for (int i = 0; i < 4; i++)
#pragma unroll
        for (int j = 0; j < 4; j++)
#pragma unroll
            for (int r = 0; r < 4; r++) acc[i][j][r] = 0.f;

    const int iters = Kpart / BK;
    float4 ra[4];
    float4 rb;

    // prologue loads (tile 0)
#pragma unroll
    for (int j = 0; j < 4; j++)
        ra[j] = *reinterpret_cast<const float4*>(&A[(long)(a_m0 + j*64) * lda + a_k]);
    if (LAYB == 0)
        rb = *reinterpret_cast<const float4*>(&B[(long)(bn + bnt_n) * ldb + bnt_k]);
    else
        rb = *reinterpret_cast<const float4*>(&B[(long)bnn_k * ldb + bn + bnn_n]);

    for (int it = 0; it < iters; ++it) {
        // commit staged regs to SMEM (convert to tf32 here, once)
#pragma unroll
        for (int j = 0; j < 4; j++) {
            unsigned* p = &As[(a_m0 + j*64) * SA + a_k];
            uint4 v;
            v.x = f2tf(ra[j].x); v.y = f2tf(ra[j].y);
            v.z = f2tf(ra[j].z); v.w = f2tf(ra[j].w);
            *reinterpret_cast<uint4*>(p) = v;
        }
        {
            uint4 v;
            v.x = f2tf(rb.x); v.y = f2tf(rb.y); v.z = f2tf(rb.z); v.w = f2tf(rb.w);
            if (LAYB == 0)
                *reinterpret_cast<uint4*>(&Bs[bnt_n * SBNT + bnt_k]) = v;
            else
                *reinterpret_cast<uint4*>(&Bs[bnn_k * SBNN + bnn_n]) = v;
        }
        __syncthreads();

        // prefetch next tile while computing this one
        const int k0n = (it + 1) * BK;
        if (it + 1 < iters) {
#pragma unroll
            for (int j = 0; j < 4; j++)
                ra[j] = *reinterpret_cast<const float4*>(&A[(long)(a_m0 + j*64) * lda + k0n + a_k]);
            if (LAYB == 0)
                rb = *reinterpret_cast<const float4*>(&B[(long)(bn + bnt_n) * ldb + k0n + bnt_k]);
            else
                rb = *reinterpret_cast<const float4*>(&B[(long)(k0n + bnn_k) * ldb + bn + bnn_n]);
        }

        // compute: two k8 steps
#pragma unroll
        for (int ks = 0; ks < BK; ks += 8) {
            unsigned af[4][4], bf[4][2];
#pragma unroll
            for (int i = 0; i < 4; i++) {
                const int mb = wm + i * 16;
                af[i][0] = As[(mb + g    ) * SA + ks + tg    ];
                af[i][1] = As[(mb + g + 8) * SA + ks + tg    ];
                af[i][2] = As[(mb + g    ) * SA + ks + tg + 4];
                af[i][3] = As[(mb + g + 8) * SA + ks + tg + 4];
            }
#pragma unroll
            for (int j = 0; j < 4; j++) {
                const int nb = wn + j * 8;
                if (LAYB == 0) {
                    bf[j][0] = Bs[(nb + g) * SBNT + ks + tg    ];
                    bf[j][1] = Bs[(nb + g) * SBNT + ks + tg + 4];
                } else {
                    bf[j][0] = Bs[(ks + tg    ) * SBNN + nb + g];
                    bf[j][1] = Bs[(ks + tg + 4) * SBNN + nb + g];
                }
            }
#pragma unroll
            for (int i = 0; i < 4; i++)
#pragma unroll
                for (int j = 0; j < 4; j++)
                    mma_tf32(acc[i][j], af[i], bf[j]);
        }
        __syncthreads();
    }

    // epilogue: c0,c1 -> (row, 2tg..2tg+1), c2,c3 -> (row+8, ...)
#pragma unroll
    for (int i = 0; i < 4; i++) {
        const int row0 = wm + i * 16 + g;
#pragma unroll
        for (int j = 0; j < 4; j++) {
            const int col = bn + wn + j * 8 + 2 * tg;
            float2 v0 = make_float2(acc[i][j][0], acc[i][j][1]);
            float2 v1 = make_float2(acc[i][j][2], acc[i][j][3]);
            *reinterpret_cast<float2*>(&C[(long)row0 * ldc + col])       = v0;
            *reinterpret_cast<float2*>(&C[(long)(row0 + 8) * ldc + col]) = v1;
        }
    }
}

// =====================================================================
// Generic NT GEMM (fp32 FFMA) for the small projections K1/K7.
// =====================================================================
template<int BM,int BN,int BK,int TM,int TN,bool BIAS>
__global__ void __launch_bounds__((BM/TM)*(BN/TN))
gemm_nt(const float* __restrict__ A, const float* __restrict__ Bm,
        const float* __restrict__ bias, float* __restrict__ C,
        int K, int lda, int ldb, int ldc,
        long sA, long sB, long sC)
{
    constexpr int TX = BN/TN, TY = BM/TM, NT = TX*TY;
    const int tid = threadIdx.x;
    const int tx  = tid % TX, ty = tid / TX;
    const int bm  = blockIdx.y*BM, bn = blockIdx.x*BN;
    A  += (long)blockIdx.z * sA;
    Bm += (long)blockIdx.z * sB;
    C  += (long)blockIdx.z * sC;

    __shared__ float As[BK][BM+4];
    __shared__ float Bs[BK][BN+4];

    float acc[TM][TN];
#pragma unroll
    for (int i=0;i<TM;i++)
#pragma unroll
        for (int j=0;j<TN;j++) acc[i][j] = 0.f;

    for (int k0 = 0; k0 < K; k0 += BK) {
#pragma unroll
        for (int i = tid; i < BM*BK/4; i += NT) {
            int m  = i / (BK/4);
            int k4 = (i % (BK/4)) * 4;
            float4 v = *reinterpret_cast<const float4*>(&A[(long)(bm+m)*lda + k0 + k4]);
            As[k4+0][m] = v.x; As[k4+1][m] = v.y; As[k4+2][m] = v.z; As[k4+3][m] = v.w;
        }
#pragma unroll
        for (int i = tid; i < BN*BK/4; i += NT) {
            int n  = i / (BK/4);
            int k4 = (i % (BK/4)) * 4;
            float4 v = *reinterpret_cast<const float4*>(&Bm[(long)(bn+n)*ldb + k0 + k4]);
            Bs[k4+0][n] = v.x; Bs[k4+1][n] = v.y; Bs[k4+2][n] = v.z; Bs[k4+3][n] = v.w;
        }
        __syncthreads();
#pragma unroll
        for (int k = 0; k < BK; k++) {
            float af[TM], bf[TN];
#pragma unroll
            for (int i=0;i<TM;i+=4)
                *reinterpret_cast<float4*>(&af[i]) =
                    *reinterpret_cast<const float4*>(&As[k][ty*TM + i]);
#pragma unroll
            for (int j=0;j<TN;j+=4)
                *reinterpret_cast<float4*>(&bf[j]) =
                    *reinterpret_cast<const float4*>(&Bs[k][tx*TN + j]);
#pragma unroll
            for (int i=0;i<TM;i++)
#pragma unroll
                for (int j=0;j<TN;j++)
                    acc[i][j] = fmaf(af[i], bf[j], acc[i][j]);
        }
        __syncthreads();
    }

#pragma unroll
    for (int i=0;i<TM;i++) {
        const int m = bm + ty*TM + i;
        float* crow = &C[(long)m*ldc + bn + tx*TN];
#pragma unroll
        for (int j=0;j<TN;j+=4) {
            float4 v;
            v.x = acc[i][j+0]; v.y = acc[i][j+1]; v.z = acc[i][j+2]; v.w = acc[i][j+3];
            if (BIAS) {
                const float* bp = &bias[bn + tx*TN + j];
                v.x += bp[0]; v.y += bp[1]; v.z += bp[2]; v.w += bp[3];
            }
            *reinterpret_cast<float4*>(&crow[j]) = v;
        }
    }
}

// =====================================================================
// qk = scale * q_h @ Wk_h : per (b,h) a 16 x 1024 output, K = 64
// =====================================================================
__global__ void qk_kernel(const float* __restrict__ q,
                          const float* __restrict__ Wk,
                          float* __restrict__ qk)
{
    const int bh = blockIdx.y;
    const int b = bh >> 4, h = bh & 15;
    const int col = blockIdx.x*128 + threadIdx.x;
    __shared__ float a[LQ][HDIM];
    for (int i = threadIdx.x; i < LQ*HDIM; i += 128) {
        int qq = i >> 6, e = i & 63;
        a[qq][e] = q[(b*LQ + qq)*HID + h*HDIM + e];
    }
    __syncthreads();
    float acc[LQ];
#pragma unroll
    for (int i=0;i<LQ;i++) acc[i] = 0.f;
#pragma unroll 8
    for (int e = 0; e < HDIM; e++) {
        float w = Wk[(h*HDIM + e)*HID + col];
#pragma unroll
        for (int qq = 0; qq < LQ; qq++) acc[qq] = fmaf(a[qq][e], w, acc[qq]);
    }
    const float scale = 0.125f;   // 1/sqrt(HDIM)
#pragma unroll
    for (int qq = 0; qq < LQ; qq++)
        qk[((long)b*RPB + h*LQ + qq)*HID + col] = acc[qq] * scale;
}

// =====================================================================
// In-place row softmax over LK=8192.
// =====================================================================
__global__ void softmax_kernel(float* __restrict__ logits)
{
    const size_t row = blockIdx.x;
    float* p = logits + row * (size_t)LK;
    __shared__ float buf[LK];
    __shared__ float red[8];
    const int tid = threadIdx.x;
    const int lane = tid & 31, warp = tid >> 5;
    float4*       b4 = reinterpret_cast<float4*>(buf);
    const float4* p4 = reinterpret_cast<const float4*>(p);

    float mx = -3.0e38f;
    for (int i = tid; i < LK/4; i += 256) {
        float4 v = p4[i]; b4[i] = v;
        mx = fmaxf(mx, fmaxf(fmaxf(v.x,v.y), fmaxf(v.z,v.w)));
    }
#pragma unroll
    for (int o=16;o;o>>=1) mx = fmaxf(mx, __shfl_xor_sync(0xffffffffu, mx, o));
    if (lane==0) red[warp] = mx;
    __syncthreads();
    mx = red[0];
#pragma unroll
    for (int w=1;w<8;w++) mx = fmaxf(mx, red[w]);

    float sum = 0.f;
    for (int i = tid; i < LK/4; i += 256) {
        float4 v = b4[i];
        v.x = expf(v.x - mx); v.y = expf(v.y - mx);
        v.z = expf(v.z - mx); v.w = expf(v.w - mx);
        b4[i] = v;
        sum += (v.x + v.y) + (v.z + v.w);
    }
#pragma unroll
    for (int o=16;o;o>>=1) sum += __shfl_xor_sync(0xffffffffu, sum, o);
    __syncthreads();
    if (lane==0) red[warp] = sum;
    __syncthreads();
    sum = 0.f;
#pragma unroll
    for (int w=0;w<8;w++) sum += red[w];
    const float inv = 1.f / sum;

    float4* o4 = reinterpret_cast<float4*>(p);
    for (int i = tid; i < LK/4; i += 256) {
        float4 v = b4[i];
        v.x *= inv; v.y *= inv; v.z *= inv; v.w *= inv;
        o4[i] = v;
    }
}

// =====================================================================
// attn[b*16+q][h*64+d] = sum_e (ctxA+ctxB)[b][h*16+q][e] * Wv[h*64+d][e] + bv
// =====================================================================
__global__ void attnv_kernel(const float* __restrict__ ctx,
                             const float* __restrict__ Wv,
                             const float* __restrict__ bv,
                             float* __restrict__ attn)
{
    const int bh = blockIdx.x;
    const int b = bh >> 4, h = bh & 15;
    const int t = threadIdx.x;
    const int d = t & 63, qg = t >> 6;
    __shared__ float cs[LQ][129];
    __shared__ float ws[HDIM][129];
    float acc[4] = {0.f,0.f,0.f,0.f};

    const long rowA = (long)(b*2    )*RPB + h*LQ;
    const long rowB = (long)(b*2 + 1)*RPB + h*LQ;

    for (int e0 = 0; e0 < HID; e0 += 128) {
        __syncthreads();
        for (int i = t; i < LQ*128; i += 256) {
            int qq = i >> 7, e = i & 127;
            cs[qq][e] = ctx[(rowA + qq)*HID + e0 + e] + ctx[(rowB + qq)*HID + e0 + e];
        }
        for (int i = t; i < HDIM*128; i += 256) {
            int dd = i >> 7, e = i & 127;
            ws[dd][e] = Wv[(long)(h*HDIM + dd)*HID + e0 + e];
        }
        __syncthreads();
#pragma unroll 4
        for (int e = 0; e < 128; e++) {
            float w = ws[d][e];
#pragma unroll
            for (int j = 0; j < 4; j++)
                acc[j] = fmaf(cs[qg*4 + j][e], w, acc[j]);
        }
    }
    const float bvv = bv[h*HDIM + d];
#pragma unroll
    for (int j = 0; j < 4; j++)
        attn[(long)(b*LQ + qg*4 + j)*HID + h*HDIM + d] = acc[j] + bvv;
}

// =====================================================================
// launch
// =====================================================================
extern "C" void kernel_launch(void* const* d_in, const int* in_sizes, int n_in,
                              void* d_out, int out_size)
{
    const float* query = (const float*)d_in[0];
    const float* key   = (const float*)d_in[1];
    const float* value = (const float*)d_in[2];
    const float* Wq    = (const float*)d_in[3];
    const float* bq    = (const float*)d_in[4];
    const float* Wk    = (const float*)d_in[5];
    /* bk = d_in[6] : softmax-invariant, dropped */
    const float* Wv    = (const float*)d_in[7];
    const float* bv    = (const float*)d_in[8];
    const float* Wo    = (const float*)d_in[9];
    const float* bo    = (const float*)d_in[10];
    float* out = (float*)d_out;

    float *gq, *gqk, *glog, *gctx, *gattn;
    cudaGetSymbolAddress((void**)&gq,    g_q);
    cudaGetSymbolAddress((void**)&gqk,   g_qk);
    cudaGetSymbolAddress((void**)&glog,  g_logits);
    cudaGetSymbolAddress((void**)&gctx,  g_ctx);
    cudaGetSymbolAddress((void**)&gattn, g_attn);

    // K1: q = query @ Wq^T + bq     [128 x 1024], K=1024  (fp32)
    gemm_nt<64,64,16,4,4,true><<<dim3(HID/64, (BB*LQ)/64, 1), 256>>>(
        query, Wq, bq, gq, HID, HID, HID, HID, 0, 0, 0);

    // K2: qk = scale * q_h @ Wk_h   [8][256][1024]  (fp32)
    qk_kernel<<<dim3(HID/128, BB*NHEAD), 128>>>(gq, Wk, gqk);

    // K3: logits = qk @ key^T       per batch [256 x 8192], K=1024  (tf32 TC)
    gemm_tf32<0><<<dim3(LK/64, 1, BB), 256>>>(
        gqk, key, glog, HID, HID, HID, LK,
        (long)RPB*HID, (long)LK*HID, (long)RPB*LK, 1);

    // K4: row softmax in place      2048 rows of 8192
    softmax_kernel<<<BB*RPB, 256>>>(glog);

    // K5: ctx = probs @ value       per batch [256 x 1024], K=8192, split-K=2  (tf32 TC)
    gemm_tf32<1><<<dim3(HID/64, 1, BB*2), 256>>>(
        glog, value, gctx, LK/2, LK, HID, HID,
        (long)RPB*LK, (long)LK*HID, (long)RPB*HID, 2);

    // K6: attn = ctx @ Wv_h^T + bv  [128 x 1024]
    attnv_kernel<<<BB*NHEAD, 256>>>(gctx, Wv, bv, gattn);

    // K7: out = attn @ Wo^T + bo    [128 x 1024], K=1024  (fp32)
    gemm_nt<64,64,16,4,4,true><<<dim3(HID/64, (BB*LQ)/64, 1), 256>>>(
        gattn, Wo, bo, out, HID, HID, HID, HID, 0, 0, 0);
}